// round 16
// baseline (speedup 1.0000x reference)
#include <cuda_runtime.h>
#include <cuda_bf16.h>
#include <math.h>
#include <stdint.h>

#define BB 8
#define TT 2048
#define II 1024
#define HH 1024
#define G4 4096
#define OO 4096
#define NB 128

typedef unsigned long long ull;

// ---------------- scratch (no allocations allowed) ----------------
__device__ float g_h[HH * BB];                 // fp32 hT (pair layout) — fc only
__device__ uint2 g_hb[2][HH / 2][BB];          // packed bf16 {hi, lo} per (kp, b)
__device__ uint2 g_xb[TT + 2][HH / 2][BB];     // x preconverted, same layout per t
__device__ uint32_t g_wfh[(size_t)NB * 32768]; // Whh frags, packed per (bid,w,j4,l,r)
__device__ uint32_t g_wfi[(size_t)NB * 32768]; // Wih frags, same packing
__device__ volatile unsigned int g_flags[NB * 32];  // one 128B line per CTA
__device__ volatile unsigned int g_sense;

__device__ __forceinline__ float tanh_fast(float x) {
    float y; asm("tanh.approx.f32 %0, %1;" : "=f"(y) : "f"(x)); return y;
}
__device__ __forceinline__ float sigmoid_fast(float x) {
    return 0.5f + 0.5f * tanh_fast(0.5f * x);
}

// ---- bf16 hi/lo split helpers ----
__device__ __forceinline__ uint32_t prmt_hi(float x, float y) {
    uint32_t r;
    asm("prmt.b32 %0, %1, %2, 0x7632;" : "=r"(r)
        : "r"(__float_as_uint(x)), "r"(__float_as_uint(y)));
    return r;
}
__device__ __forceinline__ float trunc_bf(float x) {
    return __uint_as_float(__float_as_uint(x) & 0xFFFF0000u);
}
__device__ __forceinline__ uint32_t bf2(float lo, float hi) {
    uint32_t r;
    asm("cvt.rn.bf16x2.f32 %0, %1, %2;" : "=r"(r) : "f"(hi), "f"(lo));
    return r;
}

// mma.sync m16n8k16 row.col bf16 -> f32 accumulate
#define MMA16816(d, a, b0, b1) \
    asm volatile("mma.sync.aligned.m16n8k16.row.col.f32.bf16.bf16.f32 " \
        "{%0,%1,%2,%3}, {%4,%5,%6,%7}, {%8,%9}, {%0,%1,%2,%3};" \
        : "+f"((d)[0]), "+f"((d)[1]), "+f"((d)[2]), "+f"((d)[3]) \
        : "r"((a)[0]), "r"((a)[1]), "r"((a)[2]), "r"((a)[3]), \
          "r"(b0), "r"(b1))

// no-op dummy: keeps lstm as 4th launch for ncu -s 5 alignment
__global__ void dummy_kernel() {}

// =================================================================
// conv_w: build bf16 hi/lo MMA A-fragments for Whh AND Wih, packed
//   so the lstm kernel can fetch them with coalesced 16B accesses.
//   Word j (0..63) of lane (bid,w,l):  hi: j = m*16+jt*4+r,
//   lo: j = 32+..., stored at  bid*32768 + (w*16+(j>>2))*128 + l*4 + (j&3).
// =================================================================
__global__ __launch_bounds__(512) void conv_w_kernel(
    const float* __restrict__ Whh, const float* __restrict__ Wih)
{
    const int tid = threadIdx.x;
    const int w = tid >> 5;
    const int l = tid & 31;
    const int bid = blockIdx.x;
    const int c0 = bid * 8;
    const int kb = w * 64;
    const int g = l >> 2;
    const int t4 = l & 3;

    const float* srcs[2] = {Whh, Wih};
    uint32_t* dsts[2] = {g_wfh, g_wfi};

    for (int s = 0; s < 2; s++) {
        const float* W = srcs[s];
        uint32_t words[64];
#pragma unroll
        for (int m = 0; m < 2; m++) {
            const int r0 = m * 16 + g, r1 = r0 + 8;
            const size_t wr0 = ((size_t)((r0 >> 3) * HH + c0 + (r0 & 7))) * HH;
            const size_t wr1 = ((size_t)((r1 >> 3) * HH + c0 + (r1 & 7))) * HH;
#pragma unroll
            for (int j = 0; j < 4; j++) {
                const int k0 = kb + j * 16 + 2 * t4;
                float2 p0 = *(const float2*)&W[wr0 + k0];
                float2 p1 = *(const float2*)&W[wr1 + k0];
                float2 p2 = *(const float2*)&W[wr0 + k0 + 8];
                float2 p3 = *(const float2*)&W[wr1 + k0 + 8];
                words[m * 16 + j * 4 + 0] = prmt_hi(p0.x, p0.y);
                words[m * 16 + j * 4 + 1] = prmt_hi(p1.x, p1.y);
                words[m * 16 + j * 4 + 2] = prmt_hi(p2.x, p2.y);
                words[m * 16 + j * 4 + 3] = prmt_hi(p3.x, p3.y);
                words[32 + m * 16 + j * 4 + 0] = bf2(p0.x - trunc_bf(p0.x), p0.y - trunc_bf(p0.y));
                words[32 + m * 16 + j * 4 + 1] = bf2(p1.x - trunc_bf(p1.x), p1.y - trunc_bf(p1.y));
                words[32 + m * 16 + j * 4 + 2] = bf2(p2.x - trunc_bf(p2.x), p2.y - trunc_bf(p2.y));
                words[32 + m * 16 + j * 4 + 3] = bf2(p3.x - trunc_bf(p3.x), p3.y - trunc_bf(p3.y));
            }
        }
        uint32_t* base = dsts[s] + (size_t)bid * 32768;
#pragma unroll
        for (int j = 0; j < 64; j++)
            base[(w * 16 + (j >> 2)) * 128 + l * 4 + (j & 3)] = words[j];
    }
}

// =================================================================
// conv_x: x[b][t][k] fp32 -> g_xb[t][kp][b] uint2 {hi-pair, lo-pair}
//   (identical layout to g_hb per timestep).
// =================================================================
__global__ __launch_bounds__(512) void conv_x_kernel(const float* __restrict__ x)
{
    const int t = blockIdx.x;
    const int kp = threadIdx.x;       // 0..511
    uint2 out[8];
#pragma unroll
    for (int b = 0; b < 8; b++) {
        float2 v = *(const float2*)&x[((size_t)b * TT + t) * II + 2 * kp];
        out[b].x = prmt_hi(v.x, v.y);
        out[b].y = bf2(v.x - trunc_bf(v.x), v.y - trunc_bf(v.y));
    }
    uint4* dst = (uint4*)&g_xb[t][kp][0];
#pragma unroll
    for (int i = 0; i < 4; i++) dst[i] = ((uint4*)out)[i];
}

// =================================================================
// Kernel 2: persistent recurrent LSTM + FUSED input GEMM.
//   128 CTAs x 512 thr, 1 CTA/SM. Dyn smem 208KB:
//     [0,128K)    Whh frags (loaded once from g_wfh)
//     [128K,144K) part   (rec partials, this step)
//     [144K,208K) part2  (4-slot ring of gemm slices)
//   Per step t: rec MMAs (Whh frags from smem, hb from L2) -> STS
//   part -> sync -> {tail: reduce part + part2[t&3] + bias -> gates
//   -> publish+flag} || {computes: gemm slice t+2 (Wih frags from
//   L2, xb frags from L2) -> STS part2[(t+2)&3], in tail shadow}
//   -> grid barrier (collector + hot spins, proven R13).
// =================================================================
#define CPB 8
#define NW 16
#define SM_PART 131072
#define SM_PART2 147456
#define DSM_TOTAL 212992

__global__ __launch_bounds__(512, 1) void lstm_rec_kernel(
    const float* __restrict__ bih, const float* __restrict__ bhh)
{
    extern __shared__ char dsm[];
    const uint4* s_wf4 = (const uint4*)dsm;
    float* s_part = (float*)(dsm + SM_PART);
    float* s_part2 = (float*)(dsm + SM_PART2);

    const int tid = threadIdx.x;
    const int w = tid >> 5;
    const int l = tid & 31;
    const int bid = blockIdx.x;
    const int c0 = bid * CPB;
    const int kph = w * 32;
    const int g = l >> 2;
    const int t4 = l & 3;

    // ---- prologue: copy Whh frags into smem ----
    {
        const uint4* src = (const uint4*)(g_wfh + (size_t)bid * 32768);
        uint4* dst = (uint4*)dsm;
#pragma unroll
        for (int k = 0; k < 16; k++) dst[tid + k * 512] = src[tid + k * 512];
    }

    const int rcc = tid >> 3, rb8 = tid & 7;   // tail identity (tid < 64)
    float bias0 = 0.f, bias1 = 0.f, bias2 = 0.f, bias3 = 0.f;
    if (tid < CPB * BB) {
        bias0 = bih[0 * HH + c0 + rcc] + bhh[0 * HH + c0 + rcc];
        bias1 = bih[1 * HH + c0 + rcc] + bhh[1 * HH + c0 + rcc];
        bias2 = bih[2 * HH + c0 + rcc] + bhh[2 * HH + c0 + rcc];
        bias3 = bih[3 * HH + c0 + rcc] + bhh[3 * HH + c0 + rcc];
    }

    const uint32_t* wfi_base = g_wfi + (size_t)bid * 32768;

    // ---- gemm slice (tt -> ring slot), fused macro ----
#define GEMM_SLICE(tt, slot) do { \
    uint2 xa[4], xc[4]; \
_Pragma("unroll") \
    for (int j = 0; j < 4; j++) { \
        const int kpA = kph + j * 8 + t4; \
        xa[j] = __ldcg(&g_xb[(tt)][kpA][g]); \
        xc[j] = __ldcg(&g_xb[(tt)][kpA + 4][g]); \
    } \
    float q0[4] = {0.f, 0.f, 0.f, 0.f}; \
    float q1[4] = {0.f, 0.f, 0.f, 0.f}; \
_Pragma("unroll") \
    for (int m = 0; m < 2; m++) { \
_Pragma("unroll") \
        for (int jt = 0; jt < 4; jt++) { \
            const uint4 hv = __ldcg((const uint4*)(wfi_base + ((w * 16 + m * 4 + jt) * 32 + l) * 4)); \
            const uint32_t* A = (const uint32_t*)&hv; \
            float* Q = m ? q1 : q0; \
            MMA16816(Q, A, xa[jt].x, xc[jt].x); \
            MMA16816(Q, A, xa[jt].y, xc[jt].y); \
        } \
    } \
_Pragma("unroll") \
    for (int m = 0; m < 2; m++) { \
_Pragma("unroll") \
        for (int jt = 0; jt < 4; jt++) { \
            const uint4 lv = __ldcg((const uint4*)(wfi_base + ((w * 16 + 8 + m * 4 + jt) * 32 + l) * 4)); \
            const uint32_t* A = (const uint32_t*)&lv; \
            float* Q = m ? q1 : q0; \
            MMA16816(Q, A, xa[jt].x, xc[jt].x); \
        } \
    } \
    float* pb = &s_part2[(size_t)(slot) * 4096 + (size_t)w * 256]; \
    *(float2*)&pb[(g) * 8 + t4 * 2]        = make_float2(q0[0], q0[1]); \
    *(float2*)&pb[(g + 8) * 8 + t4 * 2]    = make_float2(q0[2], q0[3]); \
    *(float2*)&pb[(g + 16) * 8 + t4 * 2]   = make_float2(q1[0], q1[1]); \
    *(float2*)&pb[(g + 24) * 8 + t4 * 2]   = make_float2(q1[2], q1[3]); \
} while (0)

    // slices for steps 0 and 1
    GEMM_SLICE(0, 0);
    GEMM_SLICE(1, 1);
    __syncthreads();

    float c_reg = 0.f;

    for (int t = 0; t < TT; t++) {
        const int rs = t & 1;
        const int wslot = rs ^ 1;

        // ---- rec MMAs: Whh frags (smem) x hb frags (L2) ----
        float d0h[4] = {0.f, 0.f, 0.f, 0.f}, d0c[4] = {0.f, 0.f, 0.f, 0.f};
        float d1h[4] = {0.f, 0.f, 0.f, 0.f}, d1c[4] = {0.f, 0.f, 0.f, 0.f};
        if (t > 0) {
            uint2 va[4], vb[4];
#pragma unroll
            for (int j = 0; j < 4; j++) {
                const int kpA = kph + j * 8 + t4;
                va[j] = __ldcg(&g_hb[rs][kpA][g]);
                vb[j] = __ldcg(&g_hb[rs][kpA + 4][g]);
            }
#pragma unroll
            for (int m = 0; m < 2; m++) {
#pragma unroll
                for (int jt = 0; jt < 4; jt++) {
                    const uint4 hv = s_wf4[(w * 16 + m * 4 + jt) * 32 + l];
                    const uint32_t* A = (const uint32_t*)&hv;
                    float* Dh = m ? d1h : d0h;
                    float* Dc = m ? d1c : d0c;
                    MMA16816(Dh, A, va[jt].x, vb[jt].x);
                    MMA16816(Dc, A, va[jt].y, vb[jt].y);
                }
            }
#pragma unroll
            for (int m = 0; m < 2; m++) {
#pragma unroll
                for (int jt = 0; jt < 4; jt++) {
                    const uint4 lv = s_wf4[(w * 16 + 8 + m * 4 + jt) * 32 + l];
                    const uint32_t* A = (const uint32_t*)&lv;
                    float* Dc = m ? d1c : d0c;
                    MMA16816(Dc, A, va[jt].x, vb[jt].x);
                }
            }
        }

        float* pw = &s_part[(size_t)w * 256];
        *(float2*)&pw[g * 8 + t4 * 2]        = make_float2(d0h[0] + d0c[0], d0h[1] + d0c[1]);
        *(float2*)&pw[(g + 8) * 8 + t4 * 2]  = make_float2(d0h[2] + d0c[2], d0h[3] + d0c[3]);
        *(float2*)&pw[(g + 16) * 8 + t4 * 2] = make_float2(d1h[0] + d1c[0], d1h[1] + d1c[1]);
        *(float2*)&pw[(g + 24) * 8 + t4 * 2] = make_float2(d1h[2] + d1c[2], d1h[3] + d1c[3]);
        __syncthreads();

        // ---- tail (tid<64): reduce rec + gemm-slice(t) + bias ----
        if (tid < CPB * BB) {
            float g0 = bias0, g1 = bias1, g2 = bias2, g3 = bias3;
            const float* p2 = &s_part2[(size_t)(t & 3) * 4096];
#pragma unroll
            for (int ww = 0; ww < NW; ww++) {
                const float* pr = &s_part[(size_t)ww * 256];
                const float* pg = &p2[(size_t)ww * 256];
                g0 += pr[(0 * 8 + rcc) * 8 + rb8] + pg[(0 * 8 + rcc) * 8 + rb8];
                g1 += pr[(1 * 8 + rcc) * 8 + rb8] + pg[(1 * 8 + rcc) * 8 + rb8];
                g2 += pr[(2 * 8 + rcc) * 8 + rb8] + pg[(2 * 8 + rcc) * 8 + rb8];
                g3 += pr[(3 * 8 + rcc) * 8 + rb8] + pg[(3 * 8 + rcc) * 8 + rb8];
            }
            const float ig = sigmoid_fast(g0);
            const float fg = sigmoid_fast(g1);
            const float gg = tanh_fast(g2);
            const float og = sigmoid_fast(g3);
            c_reg = fg * c_reg + ig * gg;
            const float h = og * tanh_fast(c_reg);

            const float ho = __shfl_down_sync(0xffffffffu, h, 8);
            if ((rcc & 1) == 0) {
                uint2 pk;
                pk.x = prmt_hi(h, ho);
                pk.y = bf2(h - trunc_bf(h), ho - trunc_bf(ho));
                g_hb[wslot][bid * 4 + (rcc >> 1)][rb8] = pk;
            }
            if (t == TT - 1) {
                const int hcol = c0 + rcc;
                g_h[(hcol >> 1) * 16 + rb8 * 2 + (hcol & 1)] = h;
            }
            asm volatile("bar.sync 1, 64;" ::: "memory");
            if (tid == 0) {
                __threadfence();
                g_flags[bid * 32] = (unsigned int)(t + 1);
            }
        }

        // ---- in the tail/barrier shadow: gemm slice for step t+2 ----
        GEMM_SLICE(t + 2, (t + 2) & 3);

        // ---- grid barrier: collector + hot spins (proven) ----
        const unsigned int tgt = (unsigned int)(t + 1);
        if (bid == 0) {
            if (tid < NB) {
                while (g_flags[tid * 32] != tgt) { }
            }
            __syncthreads();
            if (tid == 0) {
                __threadfence();
                g_sense = tgt;
            }
        } else {
            if (tid == 0) {
                while (g_sense != tgt) { }
                __threadfence();
            }
            __syncthreads();
        }
    }
#undef GEMM_SLICE
}

// =================================================================
// Kernel 3: out = hT @ W_fc^T + b_fc  (g_h, pair layout)
// =================================================================
__global__ __launch_bounds__(256) void fc_kernel(
    const float* __restrict__ Wfc, const float* __restrict__ bfc,
    float* __restrict__ out)
{
    const int o = blockIdx.x;
    const int tid = threadIdx.x;
    float acc[BB];
#pragma unroll
    for (int b = 0; b < BB; b++) acc[b] = 0.f;

    for (int k = tid; k < HH; k += 256) {
        const float wv = Wfc[(size_t)o * HH + k];
        const int base = (k >> 1) * 16 + (k & 1);
#pragma unroll
        for (int b = 0; b < BB; b++) acc[b] += wv * g_h[base + b * 2];
    }
    const int lane = tid & 31, wrp = tid >> 5;
#pragma unroll
    for (int off = 16; off; off >>= 1)
#pragma unroll
        for (int b = 0; b < BB; b++)
            acc[b] += __shfl_down_sync(0xffffffffu, acc[b], off);

    __shared__ float red[8][BB];
    if (lane == 0)
#pragma unroll
        for (int b = 0; b < BB; b++) red[wrp][b] = acc[b];
    __syncthreads();
    if (tid < BB) {
        float s = bfc[o];
#pragma unroll
        for (int ww = 0; ww < 8; ww++) s += red[ww][tid];
        out[(size_t)tid * OO + o] = s;
    }
}

// =================================================================
extern "C" void kernel_launch(void* const* d_in, const int* in_sizes, int n_in,
                              void* d_out, int out_size)
{
    const float* x    = (const float*)d_in[0];
    const float* Wih  = (const float*)d_in[1];
    const float* Whh  = (const float*)d_in[2];
    const float* bih  = (const float*)d_in[3];
    const float* bhh  = (const float*)d_in[4];
    const float* Wfc  = (const float*)d_in[5];
    const float* bfc  = (const float*)d_in[6];
    float* out = (float*)d_out;

    cudaFuncSetAttribute(lstm_rec_kernel,
                         cudaFuncAttributeMaxDynamicSharedMemorySize, DSM_TOTAL);

    dummy_kernel<<<1, 32>>>();
    conv_w_kernel<<<NB, 512>>>(Whh, Wih);
    conv_x_kernel<<<TT, 512>>>(x);
    lstm_rec_kernel<<<NB, 512, DSM_TOTAL>>>(bih, bhh);
    fc_kernel<<<OO, 256>>>(Wfc, bfc, out);
    (void)in_sizes; (void)n_in; (void)out_size;
}